// round 2
// baseline (speedup 1.0000x reference)
#include <cuda_runtime.h>
#include <cuda_bf16.h>

#define N_NODES 100000
#define N_EDGES 1600000
#define NODE_D 32
#define HID_D 64
#define GRAPH_D 32

// ---- scratch (static device globals; no runtime allocation) ----
__device__ float d_h[N_NODES * HID_D];      // 25.6 MB
__device__ float d_msg[N_NODES * HID_D];    // 25.6 MB
__device__ float d_inv[N_NODES];
__device__ int   d_deg[N_NODES];
__device__ int2  d_edges[N_EDGES];          // 12.8 MB (packed src,dst as int32)
__device__ float d_sum[HID_D];
__device__ int   d_is64;

// Probe edge_index dtype: int64 data (indices < 2^31) has every hi-word == 0.
// int32 data has random indices in the odd slots -> virtually never all zero.
__global__ void k_detect(const int* __restrict__ ei32) {
    if (threadIdx.x == 0) {
        int ok64 = 1;
        for (int i = 0; i < 64; i++) {
            if (ei32[2 * i + 1] != 0) { ok64 = 0; break; }
        }
        d_is64 = ok64;
    }
}

// Convert edge_index -> packed int2 and build in-degree histogram.
__global__ void k_convert_deg(const void* __restrict__ ei) {
    int e = blockIdx.x * blockDim.x + threadIdx.x;
    if (e < N_EDGES) {
        int s, d;
        if (d_is64) {
            const long long* p = (const long long*)ei;
            s = (int)p[e];
            d = (int)p[N_EDGES + e];
        } else {
            const int* p = (const int*)ei;
            s = p[e];
            d = p[N_EDGES + e];
        }
        d_edges[e] = make_int2(s, d);
        atomicAdd(&d_deg[d], 1);
    }
}

__global__ void k_inv() {
    int n = blockIdx.x * blockDim.x + threadIdx.x;
    if (n < N_NODES) {
        int dg = d_deg[n];
        d_inv[n] = dg > 0 ? 1.0f / (float)dg : 0.0f;
    }
}

// h = relu(x @ lin_w.T + lin_b). 4 nodes per 256-thread block, 64 threads/node.
__global__ void k_h0(const float* __restrict__ x,
                     const float* __restrict__ lw,
                     const float* __restrict__ lb) {
    __shared__ float wst[NODE_D * HID_D];  // transposed: [k][f] -> conflict-free
    __shared__ float bs[HID_D];
    __shared__ float xs[4][NODE_D];
    int tid = threadIdx.x;
    for (int i = tid; i < HID_D * NODE_D; i += 256) {
        int f = i / NODE_D, k = i % NODE_D;
        wst[k * HID_D + f] = lw[i];
    }
    if (tid < HID_D) bs[tid] = lb[tid];
    int nodeBase = blockIdx.x * 4;
    if (tid < 4 * NODE_D) {
        int n = nodeBase + tid / NODE_D;
        if (n < N_NODES) xs[tid / NODE_D][tid % NODE_D] = x[n * NODE_D + tid % NODE_D];
    }
    __syncthreads();
    int n = nodeBase + tid / HID_D;
    int f = tid % HID_D;
    if (n < N_NODES) {
        float acc = bs[f];
        const float* xr = xs[tid / HID_D];
#pragma unroll
        for (int k = 0; k < NODE_D; k++) acc += wst[k * HID_D + f] * xr[k];
        d_h[n * HID_D + f] = fmaxf(acc, 0.0f);
    }
}

// Per-edge scatter: 16 lanes per edge, each 1 float4 gather + 1 float4 red.
__global__ void k_scatter() {
    int t = blockIdx.x * blockDim.x + threadIdx.x;     // E*16 = 25.6M threads
    int e = t >> 4;
    int l = t & 15;
    if (e < N_EDGES) {
        int2 ed = d_edges[e];
        const float4 v = *reinterpret_cast<const float4*>(&d_h[ed.x * HID_D + l * 4]);
        float* p = &d_msg[ed.y * HID_D + l * 4];
        asm volatile("red.global.add.v4.f32 [%0], {%1, %2, %3, %4};"
                     :: "l"(p), "f"(v.x), "f"(v.y), "f"(v.z), "f"(v.w)
                     : "memory");
    }
}

// h = (h + msg*inv)*0.5 ; re-zero msg for the next step.
__global__ void k_update() {
    int i = blockIdx.x * blockDim.x + threadIdx.x;     // float4 index
    const int NV = N_NODES * HID_D / 4;
    if (i < NV) {
        int node = i >> 4;
        float inv = d_inv[node];
        float4 m = reinterpret_cast<float4*>(d_msg)[i];
        float4 h = reinterpret_cast<float4*>(d_h)[i];
        h.x = (h.x + m.x * inv) * 0.5f;
        h.y = (h.y + m.y * inv) * 0.5f;
        h.z = (h.z + m.z * inv) * 0.5f;
        h.w = (h.w + m.w * inv) * 0.5f;
        reinterpret_cast<float4*>(d_h)[i] = h;
        reinterpret_cast<float4*>(d_msg)[i] = make_float4(0.f, 0.f, 0.f, 0.f);
    }
}

// Final step: update + relu + per-feature sum over all nodes (pooling is linear).
__global__ void k_update_final() {
    const int NV = N_NODES * HID_D / 4;
    const int NT = gridDim.x * blockDim.x;   // multiple of 16
    int tid = threadIdx.x;
    float4 acc = make_float4(0.f, 0.f, 0.f, 0.f);
    for (int i = blockIdx.x * blockDim.x + tid; i < NV; i += NT) {
        int node = i >> 4;
        float inv = d_inv[node];
        float4 m = reinterpret_cast<float4*>(d_msg)[i];
        float4 h = reinterpret_cast<float4*>(d_h)[i];
        acc.x += fmaxf((h.x + m.x * inv) * 0.5f, 0.f);
        acc.y += fmaxf((h.y + m.y * inv) * 0.5f, 0.f);
        acc.z += fmaxf((h.z + m.z * inv) * 0.5f, 0.f);
        acc.w += fmaxf((h.w + m.w * inv) * 0.5f, 0.f);
    }
    __shared__ float4 sm[256];
    sm[tid] = acc;
    __syncthreads();
    // threads with equal tid%16 hold the same 4 features (stride NT keeps i%16 fixed)
    for (int s = 128; s >= 16; s >>= 1) {
        if (tid < s) {
            sm[tid].x += sm[tid + s].x;
            sm[tid].y += sm[tid + s].y;
            sm[tid].z += sm[tid + s].z;
            sm[tid].w += sm[tid + s].w;
        }
        __syncthreads();
    }
    if (tid < 16) {
        float4 v = sm[tid];
        atomicAdd(&d_sum[tid * 4 + 0], v.x);
        atomicAdd(&d_sum[tid * 4 + 1], v.y);
        atomicAdd(&d_sum[tid * 4 + 2], v.z);
        atomicAdd(&d_sum[tid * 4 + 3], v.w);
    }
}

// out = ((sum/N) @ pool_w.T) @ read_w.T + read_b
__global__ void k_readout(const float* __restrict__ pool_w,
                          const float* __restrict__ read_w,
                          const float* __restrict__ read_b,
                          float* __restrict__ out) {
    int tid = threadIdx.x;  // 32 threads, one per GRAPH_D feature
    float g = 0.f;
#pragma unroll
    for (int k = 0; k < HID_D; k++) g += d_sum[k] * pool_w[tid * HID_D + k];
    g *= (1.0f / N_NODES);
    float p = g * read_w[tid];
#pragma unroll
    for (int o = 16; o; o >>= 1) p += __shfl_down_sync(0xffffffffu, p, o);
    if (tid == 0) out[0] = p + read_b[0];
}

extern "C" void kernel_launch(void* const* d_in, const int* in_sizes, int n_in,
                              void* d_out, int out_size) {
    const float* x      = (const float*)d_in[0];
    const void*  ei     = d_in[1];
    const float* lin_w  = (const float*)d_in[2];
    const float* lin_b  = (const float*)d_in[3];
    const float* pool_w = (const float*)d_in[4];
    const float* read_w = (const float*)d_in[5];
    const float* read_b = (const float*)d_in[6];
    float*       out    = (float*)d_out;
    (void)in_sizes; (void)n_in; (void)out_size;

    void *pdeg = nullptr, *pmsg = nullptr, *psum = nullptr;
    cudaGetSymbolAddress(&pdeg, d_deg);
    cudaGetSymbolAddress(&pmsg, d_msg);
    cudaGetSymbolAddress(&psum, d_sum);
    cudaMemsetAsync(pdeg, 0, N_NODES * sizeof(int));
    cudaMemsetAsync(pmsg, 0, N_NODES * HID_D * sizeof(float));
    cudaMemsetAsync(psum, 0, HID_D * sizeof(float));

    k_detect<<<1, 32>>>((const int*)ei);
    k_convert_deg<<<(N_EDGES + 255) / 256, 256>>>(ei);
    k_inv<<<(N_NODES + 255) / 256, 256>>>();
    k_h0<<<(N_NODES + 3) / 4, 256>>>(x, lin_w, lin_b);

    const int scatter_blocks = (N_EDGES * 16) / 256;  // 100000 exactly
    const int upd_blocks = (N_NODES * HID_D / 4 + 255) / 256;
    for (int s = 0; s < 3; s++) {
        k_scatter<<<scatter_blocks, 256>>>();
        k_update<<<upd_blocks, 256>>>();
    }
    k_scatter<<<scatter_blocks, 256>>>();
    k_update_final<<<512, 256>>>();
    k_readout<<<1, 32>>>(pool_w, read_w, read_b, out);
}

// round 3
// speedup vs baseline: 1.7906x; 1.7906x over previous
#include <cuda_runtime.h>
#include <cuda_bf16.h>

#define N_NODES 100000
#define N_EDGES 1600000
#define NODE_D 32
#define HID_D 64
#define GRAPH_D 32
#define SCAN_B 1024
#define SCAN_NB ((N_NODES + SCAN_B - 1) / SCAN_B)   // 98

// ---- scratch (static device globals) ----
__device__ float d_ha[N_NODES * HID_D];     // 25.6 MB  ping
__device__ float d_hb[N_NODES * HID_D];     // 25.6 MB  pong
__device__ float d_inv[N_NODES];
__device__ int   d_deg[N_NODES];
__device__ int2  d_edges[N_EDGES];          // packed (src,dst) int32
__device__ int   d_srcs[N_EDGES];           // CSR: srcs sorted by dst
__device__ int   d_off[N_NODES + 1];        // CSR offsets (exclusive)
__device__ int   d_cursor[N_NODES];
__device__ int   d_partial[N_NODES];
__device__ int   d_bsum[SCAN_NB];
__device__ int   d_bbase[SCAN_NB];
__device__ float d_sum[HID_D];
__device__ int   d_is64;

// Probe edge_index dtype: int64 (indices < 2^31) has every hi-word == 0.
__global__ void k_detect(const int* __restrict__ ei32) {
    if (threadIdx.x == 0) {
        int ok64 = 1;
        for (int i = 0; i < 64; i++)
            if (ei32[2 * i + 1] != 0) { ok64 = 0; break; }
        d_is64 = ok64;
    }
}

// edge_index -> packed int2 + in-degree histogram.
__global__ void k_convert_deg(const void* __restrict__ ei) {
    int e = blockIdx.x * blockDim.x + threadIdx.x;
    if (e < N_EDGES) {
        int s, d;
        if (d_is64) {
            const long long* p = (const long long*)ei;
            s = (int)p[e];
            d = (int)p[N_EDGES + e];
        } else {
            const int* p = (const int*)ei;
            s = p[e];
            d = p[N_EDGES + e];
        }
        d_edges[e] = make_int2(s, d);
        atomicAdd(&d_deg[d], 1);
    }
}

__global__ void k_inv() {
    int n = blockIdx.x * blockDim.x + threadIdx.x;
    if (n < N_NODES) {
        int dg = d_deg[n];
        d_inv[n] = dg > 0 ? 1.0f / (float)dg : 0.0f;
    }
}

// ---- 3-phase block scan of deg -> exclusive offsets ----
__global__ void k_scan1() {
    __shared__ int sm[SCAN_B];
    int i = blockIdx.x * SCAN_B + threadIdx.x;
    sm[threadIdx.x] = (i < N_NODES) ? d_deg[i] : 0;
    __syncthreads();
    for (int s = 1; s < SCAN_B; s <<= 1) {
        int t = (threadIdx.x >= s) ? sm[threadIdx.x - s] : 0;
        __syncthreads();
        sm[threadIdx.x] += t;
        __syncthreads();
    }
    if (i < N_NODES) d_partial[i] = sm[threadIdx.x];   // inclusive within block
    if (threadIdx.x == SCAN_B - 1) d_bsum[blockIdx.x] = sm[SCAN_B - 1];
}

__global__ void k_scan2() {   // 1 block, 128 threads >= SCAN_NB
    __shared__ int sm[128];
    int t = threadIdx.x;
    sm[t] = (t < SCAN_NB) ? d_bsum[t] : 0;
    __syncthreads();
    for (int s = 1; s < 128; s <<= 1) {
        int v = (t >= s) ? sm[t - s] : 0;
        __syncthreads();
        sm[t] += v;
        __syncthreads();
    }
    if (t < SCAN_NB) d_bbase[t] = sm[t] - d_bsum[t];   // exclusive block base
}

__global__ void k_scan3() {
    int i = blockIdx.x * blockDim.x + threadIdx.x;
    if (i < N_NODES) {
        int excl = d_partial[i] - d_deg[i] + d_bbase[i / SCAN_B];
        d_off[i] = excl;
        d_cursor[i] = excl;
    }
    if (i == 0) d_off[N_NODES] = N_EDGES;
}

__global__ void k_fill() {
    int e = blockIdx.x * blockDim.x + threadIdx.x;
    if (e < N_EDGES) {
        int2 ed = d_edges[e];
        int pos = atomicAdd(&d_cursor[ed.y], 1);
        d_srcs[pos] = ed.x;
    }
}

// h = relu(x @ lin_w.T + lin_b). Weights loaded ONCE per block; block loops nodes.
#define H0_NODES_PER_BLOCK 256
__global__ void k_h0(const float* __restrict__ x,
                     const float* __restrict__ lw,
                     const float* __restrict__ lb) {
    __shared__ float wst[NODE_D * HID_D];   // [k][f]
    __shared__ float bs[HID_D];
    __shared__ float xs[4][NODE_D];
    int tid = threadIdx.x;
    for (int i = tid; i < HID_D * NODE_D; i += 256) {
        int f = i / NODE_D, k = i % NODE_D;
        wst[k * HID_D + f] = lw[i];
    }
    if (tid < HID_D) bs[tid] = lb[tid];
    int base = blockIdx.x * H0_NODES_PER_BLOCK;
    int nid = tid / HID_D;                  // 0..3
    int f = tid % HID_D;
    for (int pass = 0; pass < H0_NODES_PER_BLOCK / 4; pass++) {
        int nb = base + pass * 4;
        __syncthreads();
        if (tid < 4 * NODE_D) {
            int n = nb + tid / NODE_D;
            if (n < N_NODES) xs[tid / NODE_D][tid % NODE_D] = x[n * NODE_D + (tid % NODE_D)];
        }
        __syncthreads();
        int n = nb + nid;
        if (n < N_NODES) {
            float acc = bs[f];
            const float* xr = xs[nid];
#pragma unroll
            for (int k = 0; k < NODE_D; k++) acc += wst[k * HID_D + f] * xr[k];
            d_ha[n * HID_D + f] = fmaxf(acc, 0.0f);
        }
    }
}

// One MPNN step, CSR gather-side, fused update: hout = (hin + mean_msg)*0.5
__global__ void k_gather(const float* __restrict__ hin, float* __restrict__ hout) {
    int n = blockIdx.x * 16 + (threadIdx.x >> 4);   // node
    int l = threadIdx.x & 15;                       // float4 lane
    if (n >= N_NODES) return;
    int beg = d_off[n], end = d_off[n + 1];
    float4 acc = make_float4(0.f, 0.f, 0.f, 0.f);
    for (int i = beg; i < end; i++) {
        int s = __ldg(&d_srcs[i]);
        float4 v = *reinterpret_cast<const float4*>(&hin[s * HID_D + l * 4]);
        acc.x += v.x; acc.y += v.y; acc.z += v.z; acc.w += v.w;
    }
    float inv = d_inv[n];
    float4 h = *reinterpret_cast<const float4*>(&hin[n * HID_D + l * 4]);
    h.x = (h.x + acc.x * inv) * 0.5f;
    h.y = (h.y + acc.y * inv) * 0.5f;
    h.z = (h.z + acc.z * inv) * 0.5f;
    h.w = (h.w + acc.w * inv) * 0.5f;
    *reinterpret_cast<float4*>(&hout[n * HID_D + l * 4]) = h;
}

// Final step: gather + update + relu + per-feature sum (no h write).
__global__ void k_gather_final(const float* __restrict__ hin) {
    int tid = threadIdx.x;
    int n = blockIdx.x * 16 + (tid >> 4);
    int l = tid & 15;
    float4 r = make_float4(0.f, 0.f, 0.f, 0.f);
    if (n < N_NODES) {
        int beg = d_off[n], end = d_off[n + 1];
        float4 acc = make_float4(0.f, 0.f, 0.f, 0.f);
        for (int i = beg; i < end; i++) {
            int s = __ldg(&d_srcs[i]);
            float4 v = *reinterpret_cast<const float4*>(&hin[s * HID_D + l * 4]);
            acc.x += v.x; acc.y += v.y; acc.z += v.z; acc.w += v.w;
        }
        float inv = d_inv[n];
        float4 h = *reinterpret_cast<const float4*>(&hin[n * HID_D + l * 4]);
        r.x = fmaxf((h.x + acc.x * inv) * 0.5f, 0.f);
        r.y = fmaxf((h.y + acc.y * inv) * 0.5f, 0.f);
        r.z = fmaxf((h.z + acc.z * inv) * 0.5f, 0.f);
        r.w = fmaxf((h.w + acc.w * inv) * 0.5f, 0.f);
    }
    __shared__ float4 sm[256];
    sm[tid] = r;
    __syncthreads();
    for (int s = 128; s >= 16; s >>= 1) {       // strides are multiples of 16
        if (tid < s) {
            sm[tid].x += sm[tid + s].x;
            sm[tid].y += sm[tid + s].y;
            sm[tid].z += sm[tid + s].z;
            sm[tid].w += sm[tid + s].w;
        }
        __syncthreads();
    }
    if (tid < 16) {
        float4 v = sm[tid];
        atomicAdd(&d_sum[tid * 4 + 0], v.x);
        atomicAdd(&d_sum[tid * 4 + 1], v.y);
        atomicAdd(&d_sum[tid * 4 + 2], v.z);
        atomicAdd(&d_sum[tid * 4 + 3], v.w);
    }
}

// out = ((sum/N) @ pool_w.T) @ read_w.T + read_b
__global__ void k_readout(const float* __restrict__ pool_w,
                          const float* __restrict__ read_w,
                          const float* __restrict__ read_b,
                          float* __restrict__ out) {
    int tid = threadIdx.x;  // 32 threads, one per GRAPH_D feature
    float g = 0.f;
#pragma unroll
    for (int k = 0; k < HID_D; k++) g += d_sum[k] * pool_w[tid * HID_D + k];
    g *= (1.0f / N_NODES);
    float p = g * read_w[tid];
#pragma unroll
    for (int o = 16; o; o >>= 1) p += __shfl_down_sync(0xffffffffu, p, o);
    if (tid == 0) out[0] = p + read_b[0];
}

extern "C" void kernel_launch(void* const* d_in, const int* in_sizes, int n_in,
                              void* d_out, int out_size) {
    const float* x      = (const float*)d_in[0];
    const void*  ei     = d_in[1];
    const float* lin_w  = (const float*)d_in[2];
    const float* lin_b  = (const float*)d_in[3];
    const float* pool_w = (const float*)d_in[4];
    const float* read_w = (const float*)d_in[5];
    const float* read_b = (const float*)d_in[6];
    float*       out    = (float*)d_out;
    (void)in_sizes; (void)n_in; (void)out_size;

    void *pdeg = nullptr, *psum = nullptr;
    cudaGetSymbolAddress(&pdeg, d_deg);
    cudaGetSymbolAddress(&psum, d_sum);
    cudaMemsetAsync(pdeg, 0, N_NODES * sizeof(int));
    cudaMemsetAsync(psum, 0, HID_D * sizeof(float));

    k_detect<<<1, 32>>>((const int*)ei);
    k_convert_deg<<<(N_EDGES + 255) / 256, 256>>>(ei);
    k_inv<<<(N_NODES + 255) / 256, 256>>>();
    k_scan1<<<SCAN_NB, SCAN_B>>>();
    k_scan2<<<1, 128>>>();
    k_scan3<<<(N_NODES + 255) / 256, 256>>>();
    k_fill<<<(N_EDGES + 255) / 256, 256>>>();
    k_h0<<<(N_NODES + H0_NODES_PER_BLOCK - 1) / H0_NODES_PER_BLOCK, 256>>>(x, lin_w, lin_b);

    const int gblocks = (N_NODES + 15) / 16;   // 6250
    float *ha = nullptr, *hb = nullptr;
    cudaGetSymbolAddress((void**)&ha, d_ha);
    cudaGetSymbolAddress((void**)&hb, d_hb);
    k_gather<<<gblocks, 256>>>(ha, hb);   // step 1
    k_gather<<<gblocks, 256>>>(hb, ha);   // step 2
    k_gather<<<gblocks, 256>>>(ha, hb);   // step 3
    k_gather_final<<<gblocks, 256>>>(hb); // step 4 + pooling sum
    k_readout<<<1, 32>>>(pool_w, read_w, read_b, out);
}

// round 4
// speedup vs baseline: 1.9725x; 1.1016x over previous
#include <cuda_runtime.h>
#include <cuda_bf16.h>
#include <cuda_fp16.h>

#define N_NODES 100000
#define N_EDGES 1600000
#define NODE_D 32
#define HID_D 64
#define GRAPH_D 32
#define SCAN_B 1024
#define SCAN_NB ((N_NODES + SCAN_B - 1) / SCAN_B)   // 98

// ---- scratch (static device globals) ----
__device__ uint4 d_ha4[N_NODES * HID_D / 8];  // 12.8 MB ping (half)
__device__ uint4 d_hb4[N_NODES * HID_D / 8];  // 12.8 MB pong (half)
__device__ float d_inv[N_NODES];
__device__ int   d_deg[N_NODES];
__device__ int2  d_edges[N_EDGES];            // packed (src,dst) int32
__device__ int   d_srcs[N_EDGES];             // CSR: srcs sorted by dst
__device__ int   d_off[N_NODES + 1];          // CSR offsets (exclusive)
__device__ int   d_cursor[N_NODES];
__device__ int   d_partial[N_NODES];
__device__ int   d_bsum[SCAN_NB];
__device__ int   d_bbase[SCAN_NB];
__device__ float d_sum[HID_D];
__device__ int   d_is64;

// Probe edge_index dtype: int64 (indices < 2^31) has every hi-word == 0.
__global__ void k_detect(const int* __restrict__ ei32) {
    if (threadIdx.x == 0) {
        int ok64 = 1;
        for (int i = 0; i < 64; i++)
            if (ei32[2 * i + 1] != 0) { ok64 = 0; break; }
        d_is64 = ok64;
    }
}

// edge_index -> packed int2 + in-degree histogram.
__global__ void k_convert_deg(const void* __restrict__ ei) {
    int e = blockIdx.x * blockDim.x + threadIdx.x;
    if (e < N_EDGES) {
        int s, d;
        if (d_is64) {
            const long long* p = (const long long*)ei;
            s = (int)p[e];
            d = (int)p[N_EDGES + e];
        } else {
            const int* p = (const int*)ei;
            s = p[e];
            d = p[N_EDGES + e];
        }
        d_edges[e] = make_int2(s, d);
        atomicAdd(&d_deg[d], 1);
    }
}

__global__ void k_inv() {
    int n = blockIdx.x * blockDim.x + threadIdx.x;
    if (n < N_NODES) {
        int dg = d_deg[n];
        d_inv[n] = dg > 0 ? 1.0f / (float)dg : 0.0f;
    }
}

// ---- 3-phase block scan of deg -> exclusive offsets ----
__global__ void k_scan1() {
    __shared__ int sm[SCAN_B];
    int i = blockIdx.x * SCAN_B + threadIdx.x;
    sm[threadIdx.x] = (i < N_NODES) ? d_deg[i] : 0;
    __syncthreads();
    for (int s = 1; s < SCAN_B; s <<= 1) {
        int t = (threadIdx.x >= s) ? sm[threadIdx.x - s] : 0;
        __syncthreads();
        sm[threadIdx.x] += t;
        __syncthreads();
    }
    if (i < N_NODES) d_partial[i] = sm[threadIdx.x];   // inclusive within block
    if (threadIdx.x == SCAN_B - 1) d_bsum[blockIdx.x] = sm[SCAN_B - 1];
}

__global__ void k_scan2() {   // 1 block, 128 threads >= SCAN_NB
    __shared__ int sm[128];
    int t = threadIdx.x;
    sm[t] = (t < SCAN_NB) ? d_bsum[t] : 0;
    __syncthreads();
    for (int s = 1; s < 128; s <<= 1) {
        int v = (t >= s) ? sm[t - s] : 0;
        __syncthreads();
        sm[t] += v;
        __syncthreads();
    }
    if (t < SCAN_NB) d_bbase[t] = sm[t] - d_bsum[t];   // exclusive block base
}

__global__ void k_scan3() {
    int i = blockIdx.x * blockDim.x + threadIdx.x;
    if (i < N_NODES) {
        int excl = d_partial[i] - d_deg[i] + d_bbase[i / SCAN_B];
        d_off[i] = excl;
        d_cursor[i] = excl;
    }
    if (i == 0) d_off[N_NODES] = N_EDGES;
}

__global__ void k_fill() {
    int e = blockIdx.x * blockDim.x + threadIdx.x;
    if (e < N_EDGES) {
        int2 ed = d_edges[e];
        int pos = atomicAdd(&d_cursor[ed.y], 1);
        d_srcs[pos] = ed.x;
    }
}

// h = relu(x @ lin_w.T + lin_b), stored as fp16. Weights loaded once per block.
#define H0_NODES_PER_BLOCK 256
__global__ void k_h0(const float* __restrict__ x,
                     const float* __restrict__ lw,
                     const float* __restrict__ lb) {
    __shared__ float wst[NODE_D * HID_D];   // [k][f]
    __shared__ float bs[HID_D];
    __shared__ float xs[4][NODE_D];
    __half* H = reinterpret_cast<__half*>(d_ha4);
    int tid = threadIdx.x;
    for (int i = tid; i < HID_D * NODE_D; i += 256) {
        int f = i / NODE_D, k = i % NODE_D;
        wst[k * HID_D + f] = lw[i];
    }
    if (tid < HID_D) bs[tid] = lb[tid];
    int base = blockIdx.x * H0_NODES_PER_BLOCK;
    int nid = tid / HID_D;                  // 0..3
    int f = tid % HID_D;
    for (int pass = 0; pass < H0_NODES_PER_BLOCK / 4; pass++) {
        int nb = base + pass * 4;
        __syncthreads();
        if (tid < 4 * NODE_D) {
            int n = nb + tid / NODE_D;
            if (n < N_NODES) xs[tid / NODE_D][tid % NODE_D] = x[n * NODE_D + (tid % NODE_D)];
        }
        __syncthreads();
        int n = nb + nid;
        if (n < N_NODES) {
            float acc = bs[f];
            const float* xr = xs[nid];
#pragma unroll
            for (int k = 0; k < NODE_D; k++) acc += wst[k * HID_D + f] * xr[k];
            H[n * HID_D + f] = __float2half_rn(fmaxf(acc, 0.0f));
        }
    }
}

// One MPNN step, CSR gather-side (fp16 storage, fp32 accumulate).
// 8 lanes per node; each lane owns 8 consecutive features (one 16B load).
__global__ void k_gather(const __half* __restrict__ hin, __half* __restrict__ hout) {
    int tid = threadIdx.x;
    int n = blockIdx.x * 32 + (tid >> 3);
    int l = tid & 7;
    if (n >= N_NODES) return;
    int beg = d_off[n], end = d_off[n + 1];
    float acc[8] = {0.f, 0.f, 0.f, 0.f, 0.f, 0.f, 0.f, 0.f};
#pragma unroll 2
    for (int i = beg; i < end; i++) {
        int s = __ldg(&d_srcs[i]);
        uint4 v = *reinterpret_cast<const uint4*>(hin + s * HID_D + l * 8);
        const __half2* h2 = reinterpret_cast<const __half2*>(&v);
#pragma unroll
        for (int j = 0; j < 4; j++) {
            float2 f = __half22float2(h2[j]);
            acc[2 * j] += f.x;
            acc[2 * j + 1] += f.y;
        }
    }
    float inv = d_inv[n];
    uint4 hv = *reinterpret_cast<const uint4*>(hin + n * HID_D + l * 8);
    const __half2* hh = reinterpret_cast<const __half2*>(&hv);
    uint4 ov;
    __half2* oh = reinterpret_cast<__half2*>(&ov);
#pragma unroll
    for (int j = 0; j < 4; j++) {
        float2 f = __half22float2(hh[j]);
        float2 r;
        r.x = (f.x + acc[2 * j] * inv) * 0.5f;
        r.y = (f.y + acc[2 * j + 1] * inv) * 0.5f;
        oh[j] = __float22half2_rn(r);
    }
    *reinterpret_cast<uint4*>(hout + n * HID_D + l * 8) = ov;
}

// Final step: gather + update + relu + per-feature sum (no h write).
__global__ void k_gather_final(const __half* __restrict__ hin) {
    int tid = threadIdx.x;
    int n = blockIdx.x * 32 + (tid >> 3);
    int l = tid & 7;
    float r[8] = {0.f, 0.f, 0.f, 0.f, 0.f, 0.f, 0.f, 0.f};
    if (n < N_NODES) {
        int beg = d_off[n], end = d_off[n + 1];
        float acc[8] = {0.f, 0.f, 0.f, 0.f, 0.f, 0.f, 0.f, 0.f};
#pragma unroll 2
        for (int i = beg; i < end; i++) {
            int s = __ldg(&d_srcs[i]);
            uint4 v = *reinterpret_cast<const uint4*>(hin + s * HID_D + l * 8);
            const __half2* h2 = reinterpret_cast<const __half2*>(&v);
#pragma unroll
            for (int j = 0; j < 4; j++) {
                float2 f = __half22float2(h2[j]);
                acc[2 * j] += f.x;
                acc[2 * j + 1] += f.y;
            }
        }
        float inv = d_inv[n];
        uint4 hv = *reinterpret_cast<const uint4*>(hin + n * HID_D + l * 8);
        const __half2* hh = reinterpret_cast<const __half2*>(&hv);
#pragma unroll
        for (int j = 0; j < 4; j++) {
            float2 f = __half22float2(hh[j]);
            r[2 * j]     = fmaxf((f.x + acc[2 * j] * inv) * 0.5f, 0.f);
            r[2 * j + 1] = fmaxf((f.y + acc[2 * j + 1] * inv) * 0.5f, 0.f);
        }
    }
    __shared__ float sm[8][256];
#pragma unroll
    for (int j = 0; j < 8; j++) sm[j][tid] = r[j];
    __syncthreads();
    // strides are multiples of 8, so lane identity (tid&7) is preserved
    for (int s = 128; s >= 8; s >>= 1) {
        if (tid < s) {
#pragma unroll
            for (int j = 0; j < 8; j++) sm[j][tid] += sm[j][tid + s];
        }
        __syncthreads();
    }
    if (tid < 8) {
#pragma unroll
        for (int j = 0; j < 8; j++) atomicAdd(&d_sum[tid * 8 + j], sm[j][tid]);
    }
}

// out = ((sum/N) @ pool_w.T) @ read_w.T + read_b
__global__ void k_readout(const float* __restrict__ pool_w,
                          const float* __restrict__ read_w,
                          const float* __restrict__ read_b,
                          float* __restrict__ out) {
    int tid = threadIdx.x;  // 32 threads, one per GRAPH_D feature
    float g = 0.f;
#pragma unroll
    for (int k = 0; k < HID_D; k++) g += d_sum[k] * pool_w[tid * HID_D + k];
    g *= (1.0f / N_NODES);
    float p = g * read_w[tid];
#pragma unroll
    for (int o = 16; o; o >>= 1) p += __shfl_down_sync(0xffffffffu, p, o);
    if (tid == 0) out[0] = p + read_b[0];
}

extern "C" void kernel_launch(void* const* d_in, const int* in_sizes, int n_in,
                              void* d_out, int out_size) {
    const float* x      = (const float*)d_in[0];
    const void*  ei     = d_in[1];
    const float* lin_w  = (const float*)d_in[2];
    const float* lin_b  = (const float*)d_in[3];
    const float* pool_w = (const float*)d_in[4];
    const float* read_w = (const float*)d_in[5];
    const float* read_b = (const float*)d_in[6];
    float*       out    = (float*)d_out;
    (void)in_sizes; (void)n_in; (void)out_size;

    void *pdeg = nullptr, *psum = nullptr, *pha = nullptr, *phb = nullptr;
    cudaGetSymbolAddress(&pdeg, d_deg);
    cudaGetSymbolAddress(&psum, d_sum);
    cudaGetSymbolAddress(&pha, d_ha4);
    cudaGetSymbolAddress(&phb, d_hb4);
    cudaMemsetAsync(pdeg, 0, N_NODES * sizeof(int));
    cudaMemsetAsync(psum, 0, HID_D * sizeof(float));

    k_detect<<<1, 32>>>((const int*)ei);
    k_convert_deg<<<(N_EDGES + 255) / 256, 256>>>(ei);
    k_inv<<<(N_NODES + 255) / 256, 256>>>();
    k_scan1<<<SCAN_NB, SCAN_B>>>();
    k_scan2<<<1, 128>>>();
    k_scan3<<<(N_NODES + 255) / 256, 256>>>();
    k_fill<<<(N_EDGES + 255) / 256, 256>>>();
    k_h0<<<(N_NODES + H0_NODES_PER_BLOCK - 1) / H0_NODES_PER_BLOCK, 256>>>(x, lin_w, lin_b);

    const int gblocks = (N_NODES + 31) / 32;   // 3125
    __half* ha = (__half*)pha;
    __half* hb = (__half*)phb;
    k_gather<<<gblocks, 256>>>(ha, hb);   // step 1
    k_gather<<<gblocks, 256>>>(hb, ha);   // step 2
    k_gather<<<gblocks, 256>>>(ha, hb);   // step 3
    k_gather_final<<<gblocks, 256>>>(hb); // step 4 + pooling sum
    k_readout<<<1, 32>>>(pool_w, read_w, read_b, out);
}